// round 2
// baseline (speedup 1.0000x reference)
#include <cuda_runtime.h>

// Problem constants
#define B      128
#define CMAX   1024
#define DIN    1024
#define KTOT   2048          // 2 * DIN (complement coding)
#define NC     10
#define ALPHA  1e-3f
#define GAMMA  1e-2f

// Tiling for the choice kernel
#define C_TILE 8
#define KC     64
#define SXS    68            // padded smem stride (floats)

// -------- scratch (device globals; no allocation allowed) --------
__device__ float g_coded[B * KTOT];       // 1 MB
__device__ float g_denom[CMAX];
__device__ float g_choice[B * CMAX];      // 512 KB
__device__ float g_pmn[128];
__device__ float g_pmx[128];
__device__ float g_mn;
__device__ float g_mx;

// ---------------- 1a. per-block min/max partials ----------------
__global__ void mm_part_kernel(const float* __restrict__ x) {
    int tid = threadIdx.x;                       // 256 threads
    const float* p = x + blockIdx.x * 1024;      // 128 blocks * 1024 elems
    float mn = 3.402823466e38f, mx = -3.402823466e38f;
#pragma unroll
    for (int i = 0; i < 4; i++) {
        float v = p[tid + i * 256];
        mn = fminf(mn, v);
        mx = fmaxf(mx, v);
    }
#pragma unroll
    for (int o = 16; o; o >>= 1) {
        mn = fminf(mn, __shfl_xor_sync(0xffffffffu, mn, o));
        mx = fmaxf(mx, __shfl_xor_sync(0xffffffffu, mx, o));
    }
    __shared__ float smn[8], smx[8];
    if ((tid & 31) == 0) { smn[tid >> 5] = mn; smx[tid >> 5] = mx; }
    __syncthreads();
    if (tid == 0) {
        mn = smn[0]; mx = smx[0];
#pragma unroll
        for (int w = 1; w < 8; w++) { mn = fminf(mn, smn[w]); mx = fmaxf(mx, smx[w]); }
        g_pmn[blockIdx.x] = mn;
        g_pmx[blockIdx.x] = mx;
    }
}

// ---------------- 1b. final min/max ----------------
__global__ void mm_final_kernel() {
    int tid = threadIdx.x;                       // 128 threads
    float mn = g_pmn[tid], mx = g_pmx[tid];
#pragma unroll
    for (int o = 16; o; o >>= 1) {
        mn = fminf(mn, __shfl_xor_sync(0xffffffffu, mn, o));
        mx = fmaxf(mx, __shfl_xor_sync(0xffffffffu, mx, o));
    }
    __shared__ float smn[4], smx[4];
    if ((tid & 31) == 0) { smn[tid >> 5] = mn; smx[tid >> 5] = mx; }
    __syncthreads();
    if (tid == 0) {
        mn = fminf(fminf(smn[0], smn[1]), fminf(smn[2], smn[3]));
        mx = fmaxf(fmaxf(smx[0], smx[1]), fmaxf(smx[2], smx[3]));
        g_mn = mn;
        g_mx = mx;
    }
}

// ---------------- 2. complement coding ----------------
__global__ void coded_kernel(const float* __restrict__ x) {
    int idx = blockIdx.x * blockDim.x + threadIdx.x;   // 131072 threads
    float mn = g_mn;
    float inv = 1.0f / (g_mx - mn + 1e-10f);
    float xn = (x[idx] - mn) * inv;
    int b = idx >> 10;
    int d = idx & 1023;
    g_coded[b * KTOT + d] = xn;
    g_coded[b * KTOT + DIN + d] = 1.0f - xn;
}

// ---------------- 3. denominator per category ----------------
__global__ void denom_kernel(const float* __restrict__ templates,
                             const int* __restrict__ counts) {
    int warp = threadIdx.x >> 5, lane = threadIdx.x & 31;
    int c = blockIdx.x * 8 + warp;                     // 128 blocks * 8 warps = 1024 rows
    const float4* row = (const float4*)(templates + (size_t)c * KTOT);
    float s = 0.0f;
#pragma unroll
    for (int i = 0; i < 16; i++) {                     // 512 float4 per row / 32 lanes
        float4 v = row[lane + i * 32];
        s += (v.x + v.y) + (v.z + v.w);
    }
#pragma unroll
    for (int o = 16; o; o >>= 1)
        s += __shfl_xor_sync(0xffffffffu, s, o);
    if (lane == 0)
        g_denom[c] = ALPHA + s + GAMMA * (float)counts[c];
}

// ---------------- 4. choice matrix (the hot kernel) ----------------
// Grid: CMAX/C_TILE = 128 blocks, 256 threads.
// Thread -> b = tid & 127, c-group = tid >> 7 (4 categories each).
__global__ void __launch_bounds__(256) choice_kernel(const float* __restrict__ templates) {
    __shared__ __align__(16) float sx[B * SXS];        // ~34.8 KB
    __shared__ __align__(16) float st[C_TILE * SXS];   // ~2.2 KB

    int tid = threadIdx.x;
    int b   = tid & 127;
    int cg  = tid >> 7;                                // 0 or 1
    int cbase = blockIdx.x * C_TILE + cg * 4;

    float acc0 = 0.f, acc1 = 0.f, acc2 = 0.f, acc3 = 0.f;

    const float* xrow  = &sx[b * SXS];
    const float* trow0 = &st[(cg * 4 + 0) * SXS];
    const float* trow1 = &st[(cg * 4 + 1) * SXS];
    const float* trow2 = &st[(cg * 4 + 2) * SXS];
    const float* trow3 = &st[(cg * 4 + 3) * SXS];

    for (int k0 = 0; k0 < KTOT; k0 += KC) {
        __syncthreads();   // protect previous iteration's smem reads
        // stage x chunk: 128 rows x 16 float4
#pragma unroll
        for (int p = tid; p < 128 * 16; p += 256) {
            int bb = p >> 4, q = p & 15;
            float4 v = *(const float4*)&g_coded[bb * KTOT + k0 + q * 4];
            *(float4*)&sx[bb * SXS + q * 4] = v;
        }
        // stage template chunk: 8 rows x 16 float4
        if (tid < 128) {
            int r = tid >> 4, q = tid & 15;
            float4 v = *(const float4*)&templates[(size_t)(blockIdx.x * C_TILE + r) * KTOT + k0 + q * 4];
            *(float4*)&st[r * SXS + q * 4] = v;
        }
        __syncthreads();

#pragma unroll
        for (int q = 0; q < 16; q++) {
            float4 xv = *(const float4*)(xrow + q * 4);
            float4 t0 = *(const float4*)(trow0 + q * 4);
            float4 t1 = *(const float4*)(trow1 + q * 4);
            float4 t2 = *(const float4*)(trow2 + q * 4);
            float4 t3 = *(const float4*)(trow3 + q * 4);
            acc0 += (fminf(xv.x, t0.x) + fminf(xv.y, t0.y)) + (fminf(xv.z, t0.z) + fminf(xv.w, t0.w));
            acc1 += (fminf(xv.x, t1.x) + fminf(xv.y, t1.y)) + (fminf(xv.z, t1.z) + fminf(xv.w, t1.w));
            acc2 += (fminf(xv.x, t2.x) + fminf(xv.y, t2.y)) + (fminf(xv.z, t2.z) + fminf(xv.w, t2.w));
            acc3 += (fminf(xv.x, t3.x) + fminf(xv.y, t3.y)) + (fminf(xv.z, t3.z) + fminf(xv.w, t3.w));
        }
    }

    g_choice[b * CMAX + cbase + 0] = acc0 / g_denom[cbase + 0];
    g_choice[b * CMAX + cbase + 1] = acc1 / g_denom[cbase + 1];
    g_choice[b * CMAX + cbase + 2] = acc2 / g_denom[cbase + 2];
    g_choice[b * CMAX + cbase + 3] = acc3 / g_denom[cbase + 3];
}

// ---------------- 5. argmax + label sums + logits ----------------
// committed arrives as int32 (bool -> int32 in the harness type map)
__global__ void __launch_bounds__(256) finalize_kernel(const int* __restrict__ committed,
                                                       const int* __restrict__ labels,
                                                       float* __restrict__ out) {
    int b = blockIdx.x;
    int tid = threadIdx.x;

    float best = -3.402823466e38f;
    int   bidx = 0x7fffffff;
    float bins[NC];
#pragma unroll
    for (int l = 0; l < NC; l++) bins[l] = 0.f;

#pragma unroll
    for (int i = 0; i < 4; i++) {
        int c = tid + i * 256;
        float v = g_choice[b * CMAX + c];
        bool com = committed[c] != 0;
        int lab = labels[c];
        if (com && v > best) { best = v; bidx = c; }
        float vz = com ? v : 0.f;
#pragma unroll
        for (int l = 0; l < NC; l++)
            bins[l] += (lab == l) ? vz : 0.f;
    }

    // warp reduce (min-index tie-break == first-occurrence argmax)
#pragma unroll
    for (int o = 16; o; o >>= 1) {
        float ov = __shfl_xor_sync(0xffffffffu, best, o);
        int   oi = __shfl_xor_sync(0xffffffffu, bidx, o);
        if (ov > best || (ov == best && oi < bidx)) { best = ov; bidx = oi; }
#pragma unroll
        for (int l = 0; l < NC; l++)
            bins[l] += __shfl_xor_sync(0xffffffffu, bins[l], o);
    }

    __shared__ float s_bins[8][NC];
    __shared__ float s_best[8];
    __shared__ int   s_idx[8];
    int warp = tid >> 5, lane = tid & 31;
    if (lane == 0) {
        s_best[warp] = best;
        s_idx[warp]  = bidx;
#pragma unroll
        for (int l = 0; l < NC; l++) s_bins[warp][l] = bins[l];
    }
    __syncthreads();

    if (tid == 0) {
        best = s_best[0]; bidx = s_idx[0];
#pragma unroll
        for (int w = 1; w < 8; w++) {
            if (s_best[w] > best || (s_best[w] == best && s_idx[w] < bidx)) {
                best = s_best[w]; bidx = s_idx[w];
            }
        }
        if (bidx >= CMAX) bidx = 0;    // degenerate: nothing committed
        int plab = labels[bidx];
#pragma unroll
        for (int l = 0; l < NC; l++) {
            float tot = 0.f;
#pragma unroll
            for (int w = 0; w < 8; w++) tot += s_bins[w][l];
            out[b * NC + l] = (l == plab) ? tot : 0.f;
        }
    }
}

// ---------------- launch ----------------
extern "C" void kernel_launch(void* const* d_in, const int* in_sizes, int n_in,
                              void* d_out, int out_size) {
    const float* x         = (const float*)d_in[0];
    const float* templates = (const float*)d_in[1];
    const int*   committed = (const int*)d_in[2];     // bool -> int32
    const int*   labels    = (const int*)d_in[3];
    const int*   counts    = (const int*)d_in[4];
    float*       out       = (float*)d_out;

    mm_part_kernel<<<128, 256>>>(x);
    mm_final_kernel<<<1, 128>>>();
    coded_kernel<<<512, 256>>>(x);
    denom_kernel<<<128, 256>>>(templates, counts);
    choice_kernel<<<CMAX / C_TILE, 256>>>(templates);
    finalize_kernel<<<B, 256>>>(committed, labels, out);
}

// round 4
// speedup vs baseline: 2.2090x; 2.2090x over previous
#include <cuda_runtime.h>
#include <cstdint>

// Problem constants
#define B      128
#define CMAX   1024
#define DIN    1024
#define KTOT   2048          // 2 * DIN (complement coding)
#define NC     10
#define ALPHA  1e-3f
#define GAMMA  1e-2f

// choice kernel tiling
#define CT     8             // categories per block -> grid 128
#define KSLICE 128           // k per warp (16 warps cover 2048)
#define NITER  32            // KSLICE / 4

// -------- scratch (device globals; no allocation allowed) --------
__device__ float g_codedT[(KTOT + 4) * B];   // transposed [k][b], +4 rows pad for x prefetch overrun
__device__ float g_choice[B * CMAX];
__device__ float g_pmn[128];
__device__ float g_pmx[128];

// ---------------- 1. per-block min/max partials ----------------
__global__ void mm_part_kernel(const float* __restrict__ x) {
    int tid = threadIdx.x;                       // 256 threads
    const float* p = x + blockIdx.x * 1024;      // 128 blocks * 1024 elems
    float mn = 3.402823466e38f, mx = -3.402823466e38f;
#pragma unroll
    for (int i = 0; i < 4; i++) {
        float v = p[tid + i * 256];
        mn = fminf(mn, v);
        mx = fmaxf(mx, v);
    }
#pragma unroll
    for (int o = 16; o; o >>= 1) {
        mn = fminf(mn, __shfl_xor_sync(0xffffffffu, mn, o));
        mx = fmaxf(mx, __shfl_xor_sync(0xffffffffu, mx, o));
    }
    __shared__ float smn[8], smx[8];
    if ((tid & 31) == 0) { smn[tid >> 5] = mn; smx[tid >> 5] = mx; }
    __syncthreads();
    if (tid == 0) {
        mn = smn[0]; mx = smx[0];
#pragma unroll
        for (int w = 1; w < 8; w++) { mn = fminf(mn, smn[w]); mx = fmaxf(mx, smx[w]); }
        g_pmn[blockIdx.x] = mn;
        g_pmx[blockIdx.x] = mx;
    }
}

// ---------------- 2. normalize + complement-code + transpose ----------------
// Produces g_codedT[k][b]. Each block: 16 d-rows x 128 b. Grid 64.
__global__ void codedT_kernel(const float* __restrict__ x) {
    __shared__ float sT[16][129];
    __shared__ float rmn[8], rmx[8];
    __shared__ float s_mn, s_inv;
    int tid = threadIdx.x;                       // 256 threads

    // fold in the global min/max reduce (128 partials)
    {
        float mn = 3.402823466e38f, mx = -3.402823466e38f;
        if (tid < 128) { mn = g_pmn[tid]; mx = g_pmx[tid]; }
#pragma unroll
        for (int o = 16; o; o >>= 1) {
            mn = fminf(mn, __shfl_xor_sync(0xffffffffu, mn, o));
            mx = fmaxf(mx, __shfl_xor_sync(0xffffffffu, mx, o));
        }
        if ((tid & 31) == 0) { rmn[tid >> 5] = mn; rmx[tid >> 5] = mx; }
    }
    int d0 = blockIdx.x * 16;
#pragma unroll
    for (int p = 0; p < 8; p++) {
        int idx = tid + p * 256;                 // 0..2047
        int b = idx >> 4, dd = idx & 15;
        sT[dd][b] = x[b * 1024 + d0 + dd];
    }
    __syncthreads();
    if (tid == 0) {
        float mn = fminf(fminf(rmn[0], rmn[1]), fminf(rmn[2], rmn[3]));
        float mx = fmaxf(fmaxf(rmx[0], rmx[1]), fmaxf(rmx[2], rmx[3]));
        s_mn = mn;
        s_inv = 1.0f / (mx - mn + 1e-10f);
    }
    __syncthreads();
    float mn = s_mn, inv = s_inv;
#pragma unroll
    for (int p = 0; p < 8; p++) {
        int q = tid + p * 256;
        int dd = q >> 7, b = q & 127;
        float v = (sT[dd][b] - mn) * inv;
        g_codedT[(d0 + dd) * 128 + b] = v;
        g_codedT[(1024 + d0 + dd) * 128 + b] = 1.0f - v;
    }
}

// ---------------- 3. choice matrix + fused denominator ----------------
// Grid 128 blocks x 512 threads. Warp w handles k in [w*128, w*128+128),
// all 128 b rows (4 per lane), all 8 block categories.
// Templates staged per-warp via cp.async (4-stage ring, 3 in flight).
// x double-buffered in registers (coalesced LDG.128 from g_codedT).

#define CP_ASYNC16(dst_u32, src_ptr) \
    asm volatile("cp.async.ca.shared.global [%0], [%1], 16;" \
                 :: "r"(dst_u32), "l"(src_ptr) : "memory")
#define CP_COMMIT()  asm volatile("cp.async.commit_group;" ::: "memory")
#define CP_WAIT2()   asm volatile("cp.async.wait_group 2;" ::: "memory")

#define MATH_BODY(XX, TST)                                                                 \
    _Pragma("unroll")                                                                      \
    for (int s = 0; s < 8; s++) {                                                          \
        float4 tf = (TST)[s];                                                              \
        float a0 = fminf(XX[0].x, tf.x), a1 = fminf(XX[1].x, tf.y);                        \
        float a2 = fminf(XX[2].x, tf.z), a3 = fminf(XX[3].x, tf.w);                        \
        acc[0][s] += (a0 + a1) + (a2 + a3);                                                \
        float b0 = fminf(XX[0].y, tf.x), b1 = fminf(XX[1].y, tf.y);                        \
        float b2 = fminf(XX[2].y, tf.z), b3 = fminf(XX[3].y, tf.w);                        \
        acc[1][s] += (b0 + b1) + (b2 + b3);                                                \
        float c0 = fminf(XX[0].z, tf.x), c1 = fminf(XX[1].z, tf.y);                        \
        float c2 = fminf(XX[2].z, tf.z), c3 = fminf(XX[3].z, tf.w);                        \
        acc[2][s] += (c0 + c1) + (c2 + c3);                                                \
        float e0 = fminf(XX[0].w, tf.x), e1 = fminf(XX[1].w, tf.y);                        \
        float e2 = fminf(XX[2].w, tf.z), e3 = fminf(XX[3].w, tf.w);                        \
        acc[3][s] += (e0 + e1) + (e2 + e3);                                                \
        ulonglong2 tu = ((const ulonglong2*)(TST))[s];                                     \
        asm volatile("add.rn.f32x2 %0, %0, %1;" : "+l"(ts2[s]) : "l"(tu.x));               \
        asm volatile("add.rn.f32x2 %0, %0, %1;" : "+l"(ts2[s]) : "l"(tu.y));               \
    }

__global__ __launch_bounds__(512)
void choice_kernel(const float* __restrict__ templates,
                   const int* __restrict__ counts) {
    // all static smem, < 48KB: no cudaFuncSetAttribute needed
    __shared__ __align__(16) float stg[16 * 128];      // 8 KB: per-warp 4-stage ring
    __shared__ float sacc[8][128][9];                  // 36.9 KB (stride-9 pad)
    __shared__ float stsum[16][8];
    __shared__ float sden[8];

    int tid = threadIdx.x, w = tid >> 5, l = tid & 31;
    int cbase = blockIdx.x * CT;
    int kbase = w * KSLICE;

    float* mystg = stg + w * 128;                 // 4 stages x 32 floats
    uint32_t stg_u32 = (uint32_t)__cvta_generic_to_shared(mystg);

    const float4* xp = (const float4*)g_codedT;   // row = 32 float4s
    const float* tl = templates + (size_t)(cbase + (l & 7)) * KTOT + kbase;

    float acc[4][8];
    unsigned long long ts2[8];
#pragma unroll
    for (int r = 0; r < 4; r++)
#pragma unroll
        for (int s = 0; s < 8; s++) acc[r][s] = 0.f;
#pragma unroll
    for (int s = 0; s < 8; s++) ts2[s] = 0ull;

    // prologue: stage t(0), t(1), t(2)
#pragma unroll
    for (int p = 0; p < 3; p++) {
        if (l < 8) CP_ASYNC16(stg_u32 + (p & 3) * 128 + l * 16, tl + p * 4);
        CP_COMMIT();
    }
    float4 x0[4], x1[4];
#pragma unroll
    for (int j = 0; j < 4; j++) x0[j] = xp[(kbase + j) * 32 + l];

#pragma unroll 1
    for (int i = 0; i < NITER; i += 2) {
        // ---- consume iter i (x0) ----
        CP_WAIT2();
        __syncwarp();
        if (l < 8 && i < NITER - 3)
            CP_ASYNC16(stg_u32 + ((i + 3) & 3) * 128 + l * 16, tl + (i + 3) * 4);
        CP_COMMIT();
#pragma unroll
        for (int j = 0; j < 4; j++) x1[j] = xp[(kbase + 4 * (i + 1) + j) * 32 + l];
        {
            const float4* tst = (const float4*)(mystg + (i & 3) * 32);
            MATH_BODY(x0, tst)
        }
        // ---- consume iter i+1 (x1) ----
        CP_WAIT2();
        __syncwarp();
        if (l < 8 && i + 1 < NITER - 3)
            CP_ASYNC16(stg_u32 + ((i + 4) & 3) * 128 + l * 16, tl + (i + 4) * 4);
        CP_COMMIT();
#pragma unroll
        for (int j = 0; j < 4; j++) x0[j] = xp[(kbase + 4 * (i + 2) + j) * 32 + l];  // pad rows cover i=30
        {
            const float4* tst = (const float4*)(mystg + ((i + 1) & 3) * 32);
            MATH_BODY(x1, tst)
        }
    }

    // ---- per-warp template sums ----
    if (l == 0) {
#pragma unroll
        for (int s = 0; s < 8; s++) {
            float lo = __uint_as_float((unsigned)(ts2[s] & 0xffffffffull));
            float hi = __uint_as_float((unsigned)(ts2[s] >> 32));
            stsum[w][s] = lo + hi;
        }
    }

    // ---- staged cross-warp (k-split) reduction: 16 warps -> 8 slices -> 1 ----
    int half = w >> 1;
    if ((w & 1) == 0) {
#pragma unroll
        for (int r = 0; r < 4; r++) {
            int b = 4 * l + r;
#pragma unroll
            for (int s = 0; s < 8; s++) sacc[half][b][s] = acc[r][s];
        }
    }
    __syncthreads();
    if (w & 1) {
#pragma unroll
        for (int r = 0; r < 4; r++) {
            int b = 4 * l + r;
#pragma unroll
            for (int s = 0; s < 8; s++) sacc[half][b][s] += acc[r][s];
        }
    }
    __syncthreads();
    if (tid < 8) {
        float ssum = 0.f;
#pragma unroll
        for (int ww = 0; ww < 16; ww++) ssum += stsum[ww][tid];
        sden[tid] = ALPHA + ssum + GAMMA * (float)counts[cbase + tid];
    }
    __syncthreads();
#pragma unroll
    for (int p = tid; p < 1024; p += 512) {
        int b = p >> 3, s = p & 7;
        float v = 0.f;
#pragma unroll
        for (int hh = 0; hh < 8; hh++) v += sacc[hh][b][s];
        g_choice[b * CMAX + cbase + s] = v / sden[s];
    }
}

// ---------------- 4. argmax + label sums + logits ----------------
__global__ void __launch_bounds__(256) finalize_kernel(const int* __restrict__ committed,
                                                       const int* __restrict__ labels,
                                                       float* __restrict__ out) {
    int b = blockIdx.x;
    int tid = threadIdx.x;

    float best = -3.402823466e38f;
    int   bidx = 0x7fffffff;
    float bins[NC];
#pragma unroll
    for (int l = 0; l < NC; l++) bins[l] = 0.f;

#pragma unroll
    for (int i = 0; i < 4; i++) {
        int c = tid + i * 256;
        float v = g_choice[b * CMAX + c];
        bool com = committed[c] != 0;
        int lab = labels[c];
        if (com && v > best) { best = v; bidx = c; }
        float vz = com ? v : 0.f;
#pragma unroll
        for (int l = 0; l < NC; l++)
            bins[l] += (lab == l) ? vz : 0.f;
    }

#pragma unroll
    for (int o = 16; o; o >>= 1) {
        float ov = __shfl_xor_sync(0xffffffffu, best, o);
        int   oi = __shfl_xor_sync(0xffffffffu, bidx, o);
        if (ov > best || (ov == best && oi < bidx)) { best = ov; bidx = oi; }
#pragma unroll
        for (int l = 0; l < NC; l++)
            bins[l] += __shfl_xor_sync(0xffffffffu, bins[l], o);
    }

    __shared__ float s_bins[8][NC];
    __shared__ float s_best[8];
    __shared__ int   s_idx[8];
    int warp = tid >> 5, lane = tid & 31;
    if (lane == 0) {
        s_best[warp] = best;
        s_idx[warp]  = bidx;
#pragma unroll
        for (int l = 0; l < NC; l++) s_bins[warp][l] = bins[l];
    }
    __syncthreads();

    if (tid == 0) {
        best = s_best[0]; bidx = s_idx[0];
#pragma unroll
        for (int w = 1; w < 8; w++) {
            if (s_best[w] > best || (s_best[w] == best && s_idx[w] < bidx)) {
                best = s_best[w]; bidx = s_idx[w];
            }
        }
        if (bidx >= CMAX) bidx = 0;
        int plab = labels[bidx];
#pragma unroll
        for (int l = 0; l < NC; l++) {
            float tot = 0.f;
#pragma unroll
            for (int w = 0; w < 8; w++) tot += s_bins[w][l];
            out[b * NC + l] = (l == plab) ? tot : 0.f;
        }
    }
}

// ---------------- launch ----------------
extern "C" void kernel_launch(void* const* d_in, const int* in_sizes, int n_in,
                              void* d_out, int out_size) {
    const float* x         = (const float*)d_in[0];
    const float* templates = (const float*)d_in[1];
    const int*   committed = (const int*)d_in[2];     // bool -> int32
    const int*   labels    = (const int*)d_in[3];
    const int*   counts    = (const int*)d_in[4];
    float*       out       = (float*)d_out;

    mm_part_kernel<<<128, 256>>>(x);
    codedT_kernel<<<64, 256>>>(x);
    choice_kernel<<<CMAX / CT, 512>>>(templates, counts);
    finalize_kernel<<<B, 256>>>(committed, labels, out);
}